// round 17
// baseline (speedup 1.0000x reference)
#include <cuda_runtime.h>
#include <cuda_fp16.h>
#include <cstdint>
#include <math.h>

// ---------------------------------------------------------------------------
// MoE via fp16 mma.sync m16n8k16, cp.async(cg) 4-stage pipeline, ldmatrix,
// conflict-free (row>>1) XOR swizzle. Consumer-split convert + 4-stream overlap:
//   s2: convert13(w1,w3,sw1,sw3) ; s4: convert2(w2,sw2)
//   main: gate -> scatter -> [c13] swiglu_r(E0-7) -> [c2] down_r(E0-7) -> combine
//   s2:   [gate] swiglu_sh -> [c2] down_sh(out)
//   s3:   [c13+scatter] swiglu_r(E8-15) -> [c2] down_r(E8-15)
// ---------------------------------------------------------------------------

namespace {
constexpr int T     = 2048;
constexpr int DIMC  = 1024;
constexpr int E     = 16;
constexpr int NP    = T * 2;
constexpr int INTER = 512;
constexpr int SI    = 1024;

constexpr int BK = 32;               // halves per stage (2 k16 groups)
constexpr int STAGES = 4;
constexpr int SW_ASTG = 64 * 64;
constexpr int SW_BSTG = 128 * 64;
constexpr int SMEM_SW = STAGES * (SW_ASTG + 2 * SW_BSTG);   // 81920
constexpr int DN_ASTG = 128 * 64;
constexpr int DN_BSTG = 128 * 64;
constexpr int SMEM_DN = STAGES * (DN_ASTG + DN_BSTG);       // 65536

constexpr size_t NX = (size_t)T * DIMC;
constexpr size_t NW = (size_t)E * INTER * DIMC;
constexpr size_t NS = (size_t)SI * DIMC;
constexpr size_t GW = NW / 16;
constexpr size_t GS = NS / 16;
}

__device__ int   g_count[E];
__device__ int   g_offset[E];
__device__ int   g_pair_e[NP];
__device__ float g_pair_w[NP];
__device__ int   g_slot_of_pair[NP];
__device__ int   g_tok_of_slot[NP];
__device__ __align__(16) __half g_xh[NX];
__device__ __align__(16) __half g_w1h[NW];
__device__ __align__(16) __half g_w2h[NW];
__device__ __align__(16) __half g_w3h[NW];
__device__ __align__(16) __half g_sw1h[NS];
__device__ __align__(16) __half g_sw2h[NS];
__device__ __align__(16) __half g_sw3h[NS];
__device__ __align__(16) __half g_h[(size_t)NP * INTER];
__device__ __align__(16) __half g_hs[(size_t)T * SI];
__device__ __align__(16) float  g_rout[(size_t)NP * DIMC];

// ---------------- helpers ----------------
__device__ __forceinline__ uint32_t smem_u32(const void* p) {
    uint32_t a;
    asm("{ .reg .u64 t; cvta.to.shared.u64 t, %1; cvt.u32.u64 %0, t; }" : "=r"(a) : "l"(p));
    return a;
}
__device__ __forceinline__ void mma16(float* c, const uint32_t* a, const uint32_t* b) {
    asm volatile(
        "mma.sync.aligned.m16n8k16.row.col.f32.f16.f16.f32 "
        "{%0,%1,%2,%3},{%4,%5,%6,%7},{%8,%9},{%0,%1,%2,%3};"
        : "+f"(c[0]), "+f"(c[1]), "+f"(c[2]), "+f"(c[3])
        : "r"(a[0]), "r"(a[1]), "r"(a[2]), "r"(a[3]), "r"(b[0]), "r"(b[1]));
}
#define LDSM4(r0, r1, r2, r3, addr) \
    asm volatile("ldmatrix.sync.aligned.m8n8.x4.shared.b16 {%0,%1,%2,%3}, [%4];" \
        : "=r"(r0), "=r"(r1), "=r"(r2), "=r"(r3) : "r"(addr))
#define CP_A16(dst, src) asm volatile("cp.async.cg.shared.global [%0], [%1], 16;" :: "r"(dst), "l"(src))
#define CP_COMMIT()      asm volatile("cp.async.commit_group;" ::: "memory")
#define CP_WAIT2()       asm volatile("cp.async.wait_group 2;" ::: "memory")

// conflict-free swizzle: 64B rows, 4x16B chunks, key = (row>>1)&3
__device__ __forceinline__ uint32_t soff(int row, int c) {
    return (uint32_t)(row * 64 + ((c ^ ((row >> 1) & 3)) << 4));
}

// ---------------- converts (split by consumer) ----------------
__device__ __forceinline__ void conv16(const float* __restrict__ s, __half* __restrict__ d) {
    const float4* s4 = (const float4*)s;
    float4 v0 = s4[0], v1 = s4[1], v2 = s4[2], v3 = s4[3];
    __align__(16) __half tmp[16];
    tmp[0]=__float2half_rn(v0.x); tmp[1]=__float2half_rn(v0.y);
    tmp[2]=__float2half_rn(v0.z); tmp[3]=__float2half_rn(v0.w);
    tmp[4]=__float2half_rn(v1.x); tmp[5]=__float2half_rn(v1.y);
    tmp[6]=__float2half_rn(v1.z); tmp[7]=__float2half_rn(v1.w);
    tmp[8]=__float2half_rn(v2.x); tmp[9]=__float2half_rn(v2.y);
    tmp[10]=__float2half_rn(v2.z); tmp[11]=__float2half_rn(v2.w);
    tmp[12]=__float2half_rn(v3.x); tmp[13]=__float2half_rn(v3.y);
    tmp[14]=__float2half_rn(v3.z); tmp[15]=__float2half_rn(v3.w);
    *(uint4*)d       = *(uint4*)tmp;
    *(uint4*)(d + 8) = *(uint4*)(tmp + 8);
}

// w1, w3, sw1, sw3 (needed by SwiGLU GEMMs)
__global__ __launch_bounds__(256) void convert13_kernel(
    const float* __restrict__ w1, const float* __restrict__ w3,
    const float* __restrict__ sw1, const float* __restrict__ sw3) {
    size_t g = (size_t)blockIdx.x * 256 + threadIdx.x;
    const float* src;
    __half* dst;
    size_t off;
    if      (g < GW)              { src = w1;  dst = g_w1h;  off = g; }
    else if (g < 2 * GW)          { src = w3;  dst = g_w3h;  off = g - GW; }
    else if (g < 2 * GW + GS)     { src = sw1; dst = g_sw1h; off = g - 2 * GW; }
    else if (g < 2 * GW + 2 * GS) { src = sw3; dst = g_sw3h; off = g - 2 * GW - GS; }
    else return;
    conv16(src + off * 16, dst + off * 16);
}

// w2, sw2 (needed only by down GEMMs)
__global__ __launch_bounds__(256) void convert2_kernel(
    const float* __restrict__ w2, const float* __restrict__ sw2) {
    size_t g = (size_t)blockIdx.x * 256 + threadIdx.x;
    const float* src;
    __half* dst;
    size_t off;
    if      (g < GW)      { src = w2;  dst = g_w2h;  off = g; }
    else if (g < GW + GS) { src = sw2; dst = g_sw2h; off = g - GW; }
    else return;
    conv16(src + off * 16, dst + off * 16);
}

// ---------------- routing (+ fp16 x) ----------------
__global__ __launch_bounds__(128) void gate_kernel(const float* __restrict__ x,
                                                   const float* __restrict__ gw) {
    __shared__ float xs[DIMC];
    __shared__ float part[8][E];
    __shared__ float logit[E];
    int t = blockIdx.x;
    for (int i = threadIdx.x; i < DIMC; i += 128) xs[i] = x[(size_t)t * DIMC + i];
    __syncthreads();
    for (int i = threadIdx.x; i < DIMC; i += 128)
        g_xh[(size_t)t * DIMC + i] = __float2half_rn(xs[i]);

    int e = threadIdx.x & 15, chunk = threadIdx.x >> 4;
    const float* gr = gw + (size_t)e * DIMC + chunk * 128;
    const float* xr = xs + chunk * 128;
    float a0 = 0.f, a1 = 0.f, a2 = 0.f, a3 = 0.f;
    #pragma unroll 8
    for (int i = 0; i < 128; i += 4) {
        a0 += xr[i+0] * gr[i+0]; a1 += xr[i+1] * gr[i+1];
        a2 += xr[i+2] * gr[i+2]; a3 += xr[i+3] * gr[i+3];
    }
    part[chunk][e] = (a0 + a1) + (a2 + a3);
    __syncthreads();
    if (threadIdx.x < E) {
        float s = 0.f;
        #pragma unroll
        for (int c = 0; c < 8; c++) s += part[c][threadIdx.x];
        logit[threadIdx.x] = s;
    }
    __syncthreads();
    if (threadIdx.x == 0) {
        int i0 = 0; float v0 = logit[0];
        #pragma unroll
        for (int i = 1; i < E; i++) if (logit[i] > v0) { v0 = logit[i]; i0 = i; }
        int i1 = -1; float v1 = -1e30f;
        #pragma unroll
        for (int i = 0; i < E; i++) if (i != i0 && logit[i] > v1) { v1 = logit[i]; i1 = i; }
        float s0 = 1.f / (1.f + expf(-v0));
        float s1 = 1.f / (1.f + expf(-v1));
        float inv = 1.f / (s0 + s1);
        g_pair_e[t*2+0] = i0; g_pair_w[t*2+0] = s0 * inv;
        g_pair_e[t*2+1] = i1; g_pair_w[t*2+1] = s1 * inv;
    }
}

__global__ __launch_bounds__(1024) void scatter_kernel() {
    __shared__ int cnt[E], off[E], fill[E];
    if (threadIdx.x < E) { cnt[threadIdx.x] = 0; fill[threadIdx.x] = 0; }
    __syncthreads();
    for (int p = threadIdx.x; p < NP; p += 1024)
        atomicAdd(&cnt[g_pair_e[p]], 1);
    __syncthreads();
    if (threadIdx.x == 0) {
        int s = 0;
        #pragma unroll
        for (int e = 0; e < E; e++) {
            off[e] = s; g_offset[e] = s; g_count[e] = cnt[e]; s += cnt[e];
        }
    }
    __syncthreads();
    for (int p = threadIdx.x; p < NP; p += 1024) {
        int e = g_pair_e[p];
        int slot = off[e] + atomicAdd(&fill[e], 1);
        g_slot_of_pair[p] = slot;
        g_tok_of_slot[slot] = p >> 1;
    }
}

// ---------------------------------------------------------------------------
// SwiGLU GEMM fp16: BM=64, BN=128, dual-B, ldmatrix.
// ---------------------------------------------------------------------------
__global__ __launch_bounds__(256, 2) void swiglu_gemm(int shared_mode, int zoff) {
    extern __shared__ uint32_t sm[];
    __shared__ int rowsS[64];

    const bool routed = !shared_mode;
    const int  z      = routed ? (zoff + blockIdx.z) : 0;
    const int  Ntot   = routed ? INTER : SI;
    const int cnt  = routed ? g_count[z] : T;
    const int m0   = blockIdx.x * 64;
    if (m0 >= cnt) return;
    const int n0   = blockIdx.y * 128;
    const int base = routed ? g_offset[z] : 0;

    const __half* B1 = routed ? (g_w1h + (size_t)z * INTER * DIMC) : g_sw1h;
    const __half* B3 = routed ? (g_w3h + (size_t)z * INTER * DIMC) : g_sw3h;
    __half* C = routed ? g_h : g_hs;

    const int tid    = threadIdx.x;
    const int wid    = tid >> 5;
    const int lane   = tid & 31;
    const int lane4  = lane >> 2;
    const int lanek  = lane & 3;
    const int warp_m = wid & 1;
    const int warp_n = wid >> 1;

    if (tid < 64) {
        int m = m0 + tid;
        rowsS[tid] = routed ? g_tok_of_slot[base + min(m, cnt - 1)]
                            : min(m, cnt - 1);
    }
    __syncthreads();

    const uint32_t smA = smem_u32(sm);
    const uint32_t smB = smA + STAGES * SW_ASTG;
    const uint32_t smC = smB + STAGES * SW_BSTG;

    const int ar = tid >> 2, ac = tid & 3;
    const __half* asrc = g_xh + (size_t)rowsS[ar] * DIMC + ac * 8;
    const __half* b1s0 = B1 + (size_t)(n0 + ar) * DIMC + ac * 8;
    const __half* b1s1 = B1 + (size_t)(n0 + 64 + ar) * DIMC + ac * 8;
    const __half* b3s0 = B3 + (size_t)(n0 + ar) * DIMC + ac * 8;
    const __half* b3s1 = B3 + (size_t)(n0 + 64 + ar) * DIMC + ac * 8;
    const uint32_t adst  = smA + soff(ar, ac);
    const uint32_t bdst0 = smB + soff(ar, ac);
    const uint32_t bdst1 = smB + soff(64 + ar, ac);
    const uint32_t cdst0 = smC + soff(ar, ac);
    const uint32_t cdst1 = smC + soff(64 + ar, ac);

    auto issue = [&](int k0, int st) {
        if (k0 < DIMC) {
            CP_A16(adst  + st * SW_ASTG, asrc + k0);
            CP_A16(bdst0 + st * SW_BSTG, b1s0 + k0);
            CP_A16(bdst1 + st * SW_BSTG, b1s1 + k0);
            CP_A16(cdst0 + st * SW_BSTG, b3s0 + k0);
            CP_A16(cdst1 + st * SW_BSTG, b3s1 + k0);
        }
        CP_COMMIT();
    };

    issue(0, 0); issue(BK, 1); issue(2 * BK, 2);

    const int mat  = lane >> 3, mrow = lane & 7;
    const int cbA  = mat >> 1;
    const int cbB  = mat & 1;
    int arow[2], akey[2], brow[2], bkey[2];
    #pragma unroll
    for (int fm = 0; fm < 2; fm++) {
        int r = warp_m * 32 + fm * 16 + ((mat & 1) << 3) + mrow;
        arow[fm] = r * 64; akey[fm] = (r >> 1) & 3;
    }
    #pragma unroll
    for (int fn2 = 0; fn2 < 2; fn2++) {
        int r = warp_n * 32 + fn2 * 16 + ((mat >> 1) << 3) + mrow;
        brow[fn2] = r * 64; bkey[fn2] = (r >> 1) & 3;
    }

    float acc1[2][4][4] = {};
    float acc3[2][4][4] = {};

    int st = 0;
    for (int k0 = 0; k0 < DIMC; k0 += BK) {
        CP_WAIT2();
        __syncthreads();
        const uint32_t aSt = smA + st * SW_ASTG;
        const uint32_t bSt = smB + st * SW_BSTG;
        const uint32_t cSt = smC + st * SW_BSTG;

        #pragma unroll
        for (int g = 0; g < 2; g++) {
            uint32_t af[2][4];
            #pragma unroll
            for (int fm = 0; fm < 2; fm++) {
                uint32_t ad = aSt + arow[fm] + ((((g << 1) + cbA) ^ akey[fm]) << 4);
                LDSM4(af[fm][0], af[fm][1], af[fm][2], af[fm][3], ad);
            }
            #pragma unroll
            for (int fn2 = 0; fn2 < 2; fn2++) {
                uint32_t boff = brow[fn2] + ((((g << 1) + cbB) ^ bkey[fn2]) << 4);
                uint32_t bf[4], cf[4];
                LDSM4(bf[0], bf[1], bf[2], bf[3], bSt + boff);
                LDSM4(cf[0], cf[1], cf[2], cf[3], cSt + boff);
                mma16(acc1[0][fn2 * 2 + 0], af[0], bf + 0);
                mma16(acc1[0][fn2 * 2 + 1], af[0], bf + 2);
                mma16(acc1[1][fn2 * 2 + 0], af[1], bf + 0);
                mma16(acc1[1][fn2 * 2 + 1], af[1], bf + 2);
                mma16(acc3[0][fn2 * 2 + 0], af[0], cf + 0);
                mma16(acc3[0][fn2 * 2 + 1], af[0], cf + 2);
                mma16(acc3[1][fn2 * 2 + 0], af[1], cf + 0);
                mma16(acc3[1][fn2 * 2 + 1], af[1], cf + 2);
            }
        }
        issue(k0 + 3 * BK, (k0 / BK + 3) & (STAGES - 1));
        st = (st + 1) & (STAGES - 1);
    }

    #pragma unroll
    for (int fm = 0; fm < 2; fm++) {
        #pragma unroll
        for (int half = 0; half < 2; half++) {
            int mi = warp_m * 32 + fm * 16 + half * 8 + lane4;
            int m  = m0 + mi;
            if (m >= cnt) continue;
            size_t crow = routed ? (size_t)(base + m) : (size_t)m;
            #pragma unroll
            for (int fn = 0; fn < 4; fn++) {
                int c = n0 + warp_n * 32 + fn * 8 + lanek * 2;
                float v0 = acc1[fm][fn][half * 2 + 0];
                float v1 = acc1[fm][fn][half * 2 + 1];
                float sx = (v0 / (1.f + __expf(-v0))) * acc3[fm][fn][half * 2 + 0];
                float sy = (v1 / (1.f + __expf(-v1))) * acc3[fm][fn][half * 2 + 1];
                *(__half2*)(C + crow * Ntot + c) = __floats2half2_rn(sx, sy);
            }
        }
    }
}

// ---------------------------------------------------------------------------
// Down GEMM fp16: BM=128, BN=128, warp 64x32, ldmatrix.
// ---------------------------------------------------------------------------
__global__ __launch_bounds__(256, 2) void down_gemm(int shared_mode, int zoff,
                                                    float* __restrict__ out) {
    extern __shared__ uint32_t sm[];
    __shared__ int rowsS[128];

    const bool routed = !shared_mode;
    const int  z      = routed ? (zoff + blockIdx.z) : 0;
    const int  KD     = routed ? INTER : SI;
    const int cnt  = routed ? g_count[z] : T;
    const int m0   = blockIdx.x * 128;
    if (m0 >= cnt) return;
    const int n0   = blockIdx.y * 128;
    const int base = routed ? g_offset[z] : 0;

    const __half* A  = routed ? g_h : g_hs;
    const __half* B1 = routed ? (g_w2h + (size_t)z * DIMC * INTER) : g_sw2h;
    float* C = routed ? g_rout : out;

    const int tid    = threadIdx.x;
    const int wid    = tid >> 5;
    const int lane   = tid & 31;
    const int lane4  = lane >> 2;
    const int lanek  = lane & 3;
    const int warp_m = wid & 1;
    const int warp_n = wid >> 1;

    if (tid < 128) {
        int mm = m0 + tid;
        if (mm >= cnt) mm = cnt - 1;
        rowsS[tid] = routed ? (base + mm) : mm;
    }
    __syncthreads();

    const uint32_t smA = smem_u32(sm);
    const uint32_t smB = smA + STAGES * DN_ASTG;

    const int ar0 = tid >> 2, ar1 = 64 + (tid >> 2), ac = tid & 3;
    const __half* asrc0 = A  + (size_t)rowsS[ar0] * KD + ac * 8;
    const __half* asrc1 = A  + (size_t)rowsS[ar1] * KD + ac * 8;
    const __half* bsrc0 = B1 + (size_t)(n0 + ar0) * KD + ac * 8;
    const __half* bsrc1 = B1 + (size_t)(n0 + ar1) * KD + ac * 8;
    const uint32_t adst0 = smA + soff(ar0, ac);
    const uint32_t adst1 = smA + soff(ar1, ac);
    const uint32_t bdst0 = smB + soff(ar0, ac);
    const uint32_t bdst1 = smB + soff(ar1, ac);

    auto issue = [&](int k0, int st) {
        if (k0 < KD) {
            CP_A16(adst0 + st * DN_ASTG, asrc0 + k0);
            CP_A16(adst1 + st * DN_ASTG, asrc1 + k0);
            CP_A16(bdst0 + st * DN_BSTG, bsrc0 + k0);
            CP_A16(bdst1 + st * DN_BSTG, bsrc1 + k0);
        }
        CP_COMMIT();
    };

    issue(0, 0); issue(BK, 1); issue(2 * BK, 2);

    const int mat  = lane >> 3, mrow = lane & 7;
    const int cbA  = mat >> 1;
    const int cbB  = mat & 1;
    int arow[4], akey[4], brow[2], bkey[2];
    #pragma unroll
    for (int fm = 0; fm < 4; fm++) {
        int r = warp_m * 64 + fm * 16 + ((mat & 1) << 3) + mrow;
        arow[fm] = r * 64; akey[fm] = (r >> 1) & 3;
    }
    #pragma unroll
    for (int fn2 = 0; fn2 < 2; fn2++) {
        int r = warp_n * 32 + fn2 * 16 + ((mat >> 1) << 3) + mrow;
        brow[fn2] = r * 64; bkey[fn2] = (r >> 1) & 3;
    }

    float acc[4][4][4] = {};

    int st = 0;
    for (int k0 = 0; k0 < KD; k0 += BK) {
        CP_WAIT2();
        __syncthreads();
        const uint32_t aSt = smA + st * DN_ASTG;
        const uint32_t bSt = smB + st * DN_BSTG;

        #pragma unroll
        for (int g = 0; g < 2; g++) {
            uint32_t af[4][4];
            #pragma unroll
            for (int fm = 0; fm < 4; fm++) {
                uint32_t ad = aSt + arow[fm] + ((((g << 1) + cbA) ^ akey[fm]) << 4);
                LDSM4(af[fm][0], af[fm][1], af[fm][2], af[fm][3], ad);
            }
            #pragma unroll
            for (int fn2 = 0; fn2 < 2; fn2++) {
                uint32_t bf[4];
                uint32_t boff = brow[fn2] + ((((g << 1) + cbB) ^ bkey[fn2]) << 4);
                LDSM4(bf[0], bf[1], bf[2], bf[3], bSt + boff);
                #pragma unroll
                for (int fm = 0; fm < 4; fm++) {
                    mma16(acc[fm][fn2 * 2 + 0], af[fm], bf + 0);
                    mma16(acc[fm][fn2 * 2 + 1], af[fm], bf + 2);
                }
            }
        }
        issue(k0 + 3 * BK, (k0 / BK + 3) & (STAGES - 1));
        st = (st + 1) & (STAGES - 1);
    }

    #pragma unroll
    for (int fm = 0; fm < 4; fm++) {
        #pragma unroll
        for (int half = 0; half < 2; half++) {
            int mi = warp_m * 64 + fm * 16 + half * 8 + lane4;
            int m  = m0 + mi;
            if (m >= cnt) continue;
            size_t crow = routed ? (size_t)(base + m) : (size_t)m;
            float* cp = C + crow * DIMC + n0 + warp_n * 32 + lanek * 2;
            #pragma unroll
            for (int fn = 0; fn < 4; fn++) {
                float2 o;
                o.x = acc[fm][fn][half * 2 + 0];
                o.y = acc[fm][fn][half * 2 + 1];
                *(float2*)(cp + fn * 8) = o;
            }
        }
    }
}

__global__ __launch_bounds__(256) void combine_kernel(float* __restrict__ out) {
    int t = blockIdx.x;
    float w0 = g_pair_w[t*2+0], w1 = g_pair_w[t*2+1];
    size_t s0 = (size_t)g_slot_of_pair[t*2+0] * DIMC;
    size_t s1 = (size_t)g_slot_of_pair[t*2+1] * DIMC;
    int d = threadIdx.x * 4;
    float4 o  = *(float4*)(out + (size_t)t * DIMC + d);
    float4 r0 = *(const float4*)(g_rout + s0 + d);
    float4 r1 = *(const float4*)(g_rout + s1 + d);
    o.x += w0 * r0.x + w1 * r1.x;
    o.y += w0 * r0.y + w1 * r1.y;
    o.z += w0 * r0.z + w1 * r1.z;
    o.w += w0 * r0.w + w1 * r1.w;
    *(float4*)(out + (size_t)t * DIMC + d) = o;
}

// ---------------------------------------------------------------------------
extern "C" void kernel_launch(void* const* d_in, const int* in_sizes, int n_in,
                              void* d_out, int out_size) {
    const float* x      = (const float*)d_in[0];
    const float* gate_w = (const float*)d_in[1];
    const float* w1     = (const float*)d_in[2];
    const float* w2     = (const float*)d_in[3];
    const float* w3     = (const float*)d_in[4];
    const float* sw1    = (const float*)d_in[5];
    const float* sw2    = (const float*)d_in[6];
    const float* sw3    = (const float*)d_in[7];
    float* out = (float*)d_out;

    static cudaStream_t s2 = nullptr, s3 = nullptr, s4 = nullptr;
    static cudaEvent_t evFork, evC13, evC2, evGate, evScat, evShared, evR2;
    if (s2 == nullptr) {
        cudaStreamCreateWithFlags(&s2, cudaStreamNonBlocking);
        cudaStreamCreateWithFlags(&s3, cudaStreamNonBlocking);
        cudaStreamCreateWithFlags(&s4, cudaStreamNonBlocking);
        cudaEventCreateWithFlags(&evFork,   cudaEventDisableTiming);
        cudaEventCreateWithFlags(&evC13,    cudaEventDisableTiming);
        cudaEventCreateWithFlags(&evC2,     cudaEventDisableTiming);
        cudaEventCreateWithFlags(&evGate,   cudaEventDisableTiming);
        cudaEventCreateWithFlags(&evScat,   cudaEventDisableTiming);
        cudaEventCreateWithFlags(&evShared, cudaEventDisableTiming);
        cudaEventCreateWithFlags(&evR2,     cudaEventDisableTiming);
        cudaFuncSetAttribute(swiglu_gemm, cudaFuncAttributeMaxDynamicSharedMemorySize, SMEM_SW);
        cudaFuncSetAttribute(down_gemm,   cudaFuncAttributeMaxDynamicSharedMemorySize, SMEM_DN);
    }

    // fork
    cudaEventRecord(evFork, 0);
    cudaStreamWaitEvent(s2, evFork, 0);
    cudaStreamWaitEvent(s3, evFork, 0);
    cudaStreamWaitEvent(s4, evFork, 0);

    // s2: convert SwiGLU weights (w1,w3,sw1,sw3)
    size_t n13 = 2 * GW + 2 * GS;
    convert13_kernel<<<(int)((n13 + 255) / 256), 256, 0, s2>>>(w1, w3, sw1, sw3);
    cudaEventRecord(evC13, s2);

    // s4: convert down weights (w2,sw2) — consumed later, overlaps SwiGLU phase
    size_t n2 = GW + GS;
    convert2_kernel<<<(int)((n2 + 255) / 256), 256, 0, s4>>>(w2, sw2);
    cudaEventRecord(evC2, s4);

    // main: routing
    gate_kernel<<<T, 128>>>(x, gate_w);
    cudaEventRecord(evGate, 0);
    scatter_kernel<<<1, 1024>>>();
    cudaEventRecord(evScat, 0);

    // s2: shared chain (conv13 by stream order; needs g_xh from gate; down needs conv2)
    cudaStreamWaitEvent(s2, evGate, 0);
    swiglu_gemm<<<dim3(T / 64, SI / 128, 1), 256, SMEM_SW, s2>>>(1, 0);
    cudaStreamWaitEvent(s2, evC2, 0);
    down_gemm<<<dim3(T / 128, DIMC / 128, 1), 256, SMEM_DN, s2>>>(1, 0, out);
    cudaEventRecord(evShared, s2);

    // s3: routed chain, experts 8..15
    cudaStreamWaitEvent(s3, evC13, 0);
    cudaStreamWaitEvent(s3, evScat, 0);
    swiglu_gemm<<<dim3(T / 64, INTER / 128, E / 2), 256, SMEM_SW, s3>>>(0, E / 2);
    cudaStreamWaitEvent(s3, evC2, 0);
    down_gemm<<<dim3(T / 128, DIMC / 128, E / 2), 256, SMEM_DN, s3>>>(0, E / 2, nullptr);
    cudaEventRecord(evR2, s3);

    // main: routed chain, experts 0..7
    cudaStreamWaitEvent(0, evC13, 0);
    swiglu_gemm<<<dim3(T / 64, INTER / 128, E / 2), 256, SMEM_SW>>>(0, 0);
    cudaStreamWaitEvent(0, evC2, 0);
    down_gemm<<<dim3(T / 128, DIMC / 128, E / 2), 256, SMEM_DN>>>(0, 0, nullptr);

    // join
    cudaStreamWaitEvent(0, evShared, 0);
    cudaStreamWaitEvent(0, evR2, 0);
    combine_kernel<<<T, 256>>>(out);
}